// round 2
// baseline (speedup 1.0000x reference)
#include <cuda_runtime.h>
#include <math.h>

#define H 128
#define B 512
#define RANKS 3
#define POOL_BLOCKS 512
#define POOL_THREADS 256
#define POOL_WARPS (POOL_BLOCKS * POOL_THREADS / 32)

// ---------------- scratch (no allocations allowed) ----------------
__device__ float g_sum [RANKS][B * H];
__device__ float g_gsum[RANKS][B * H];
__device__ float g_max [RANKS][B * H];
__device__ float g_cnt [RANKS][B];
__device__ float g_state[B][3 * H];

__device__ __forceinline__ void atomicMaxF(float* addr, float v) {
    if (v >= 0.f) atomicMax((int*)addr, __float_as_int(v));
    else          atomicMin((unsigned int*)addr, __float_as_uint(v));
}

// ---------------- init: reset accumulators every replay ----------------
__global__ void init_kernel() {
    int i = blockIdx.x * blockDim.x + threadIdx.x;
    int stride = gridDim.x * blockDim.x;
    int tot = RANKS * B * H;
    for (int idx = i; idx < tot; idx += stride) {
        int r = idx / (B * H);
        int o = idx - r * (B * H);
        g_sum[r][o]  = 0.f;
        g_gsum[r][o] = 0.f;
        g_max[r][o]  = -INFINITY;
    }
    if (i < RANKS * B) g_cnt[i / B][i % B] = 0.f;
}

// ---------------- stage 1: gated multi-agg pooling ----------------
// One warp per contiguous node strip. Lane owns 4 columns (float4).
// Segment ids are sorted -> register accumulation, atomic flush at boundaries.
__global__ void pool_kernel(const float* __restrict__ h,
                            const int*   __restrict__ b,
                            const float* __restrict__ Wg,
                            const float* __restrict__ bg,
                            int N, int rank, int npw) {
    int gwid = (blockIdx.x * blockDim.x + threadIdx.x) >> 5;
    int lane = threadIdx.x & 31;
    int start = gwid * npw;
    if (start >= N) return;
    int end = min(N, start + npw);

    float4 wg = reinterpret_cast<const float4*>(Wg)[lane];
    float bgv = bg[0];

    float* __restrict__ sums  = g_sum[rank];
    float* __restrict__ gsums = g_gsum[rank];
    float* __restrict__ maxs  = g_max[rank];
    float* __restrict__ cnts  = g_cnt[rank];

    int cur = b[start];
    float4 s4  = make_float4(0.f, 0.f, 0.f, 0.f);
    float4 gs4 = make_float4(0.f, 0.f, 0.f, 0.f);
    float4 m4  = make_float4(-INFINITY, -INFINITY, -INFINITY, -INFINITY);
    float  c   = 0.f;

    auto flush = [&]() {
        int base = cur * H + (lane << 2);
        atomicAdd(&sums[base + 0], s4.x);
        atomicAdd(&sums[base + 1], s4.y);
        atomicAdd(&sums[base + 2], s4.z);
        atomicAdd(&sums[base + 3], s4.w);
        atomicAdd(&gsums[base + 0], gs4.x);
        atomicAdd(&gsums[base + 1], gs4.y);
        atomicAdd(&gsums[base + 2], gs4.z);
        atomicAdd(&gsums[base + 3], gs4.w);
        atomicMaxF(&maxs[base + 0], m4.x);
        atomicMaxF(&maxs[base + 1], m4.y);
        atomicMaxF(&maxs[base + 2], m4.z);
        atomicMaxF(&maxs[base + 3], m4.w);
        if (lane == 0) atomicAdd(&cnts[cur], c);
    };

    for (int n = start; n < end; ++n) {
        int seg = b[n];
        float4 v = reinterpret_cast<const float4*>(h)[n * 32 + lane];
        if (seg != cur) {
            flush();
            s4  = make_float4(0.f, 0.f, 0.f, 0.f);
            gs4 = make_float4(0.f, 0.f, 0.f, 0.f);
            m4  = make_float4(-INFINITY, -INFINITY, -INFINITY, -INFINITY);
            c   = 0.f;
            cur = seg;
        }
        float p = v.x * wg.x + v.y * wg.y + v.z * wg.z + v.w * wg.w;
        #pragma unroll
        for (int o = 16; o; o >>= 1) p += __shfl_xor_sync(0xffffffffu, p, o);
        float z = p + bgv;
        float g = 1.f / (1.f + __expf(-z));
        s4.x += v.x;  s4.y += v.y;  s4.z += v.z;  s4.w += v.w;
        m4.x = fmaxf(m4.x, v.x);  m4.y = fmaxf(m4.y, v.y);
        m4.z = fmaxf(m4.z, v.z);  m4.w = fmaxf(m4.w, v.w);
        gs4.x += g * v.x;  gs4.y += g * v.y;  gs4.z += g * v.z;  gs4.w += g * v.w;
        c += 1.f;
    }
    flush();
}

// ---------------- stage 2: [B,4H] @ Wp[4H,H] + bp -> state slice ----------------
// grid: (B/16, 3 ranks), 256 threads (128 output cols x 2 K-halves)
__global__ void proj_kernel(const float* __restrict__ Wp0, const float* __restrict__ bp0,
                            const float* __restrict__ Wp1, const float* __restrict__ bp1,
                            const float* __restrict__ Wp2, const float* __restrict__ bp2) {
    int rank = blockIdx.y;
    const float* Wp = (rank == 0) ? Wp0 : (rank == 1) ? Wp1 : Wp2;
    const float* bp = (rank == 0) ? bp0 : (rank == 1) ? bp1 : bp2;
    int seg0 = blockIdx.x * 16;
    int tid = threadIdx.x;

    __shared__ float a[16][512];    // agg tile, k-major
    __shared__ float cs[16];
    __shared__ float rh[16][128];

    const float* __restrict__ sums  = g_sum[rank];
    const float* __restrict__ gsums = g_gsum[rank];
    const float* __restrict__ maxs  = g_max[rank];

    if (tid < 16) cs[tid] = g_cnt[rank][seg0 + tid];
    __syncthreads();

    for (int idx = tid; idx < 16 * 512; idx += 256) {
        int s = idx >> 9;
        int k = idx & 511;
        int seg = seg0 + s;
        float v;
        if (k < 128)      v = sums[seg * H + k];
        else if (k < 256) v = sums[seg * H + (k - 128)] / fmaxf(cs[s], 1.f);
        else if (k < 384) v = (cs[s] > 0.f) ? maxs[seg * H + (k - 256)] : 0.f;
        else              v = gsums[seg * H + (k - 384)];
        a[s][k] = v;
    }
    __syncthreads();

    int j = tid & 127;
    int half = tid >> 7;
    int k0 = half * 256;
    float r[16];
    #pragma unroll
    for (int s = 0; s < 16; ++s) r[s] = 0.f;

    const float* Wph = Wp + k0 * H + j;
    for (int kg = 0; kg < 64; ++kg) {
        float w0 = Wph[(kg * 4 + 0) * H];
        float w1 = Wph[(kg * 4 + 1) * H];
        float w2 = Wph[(kg * 4 + 2) * H];
        float w3 = Wph[(kg * 4 + 3) * H];
        #pragma unroll
        for (int s = 0; s < 16; ++s) {
            float4 av = reinterpret_cast<const float4*>(&a[s][k0])[kg];
            r[s] += av.x * w0 + av.y * w1 + av.z * w2 + av.w * w3;
        }
    }

    if (half == 1) {
        #pragma unroll
        for (int s = 0; s < 16; ++s) rh[s][j] = r[s];
    }
    __syncthreads();
    if (half == 0) {
        float bpj = bp[j];
        #pragma unroll
        for (int s = 0; s < 16; ++s)
            g_state[seg0 + s][rank * H + j] = r[s] + rh[s][j] + bpj;
    }
}

// ---------------- stage 3: LN + SiLU + MLP + final dot ----------------
// grid: B/16 blocks, 256 threads
__global__ void final_kernel(const float* __restrict__ gamma, const float* __restrict__ beta,
                             const float* __restrict__ W1,    const float* __restrict__ b1f,
                             const float* __restrict__ W2,    const float* __restrict__ b2f,
                             float* __restrict__ out) {
    int seg0 = blockIdx.x * 16;
    int tid = threadIdx.x;
    int wid = tid >> 5;
    int lane = tid & 31;

    __shared__ float a[16][384];
    __shared__ float rh[16][128];

    for (int idx = tid; idx < 16 * 384; idx += 256) {
        int s = idx / 384;
        int k = idx - s * 384;
        a[s][k] = g_state[seg0 + s][k];
    }
    __syncthreads();

    // per-row LayerNorm + SiLU, warp handles rows wid, wid+8
    for (int s = wid; s < 16; s += 8) {
        float ps = 0.f;
        for (int k = lane; k < 384; k += 32) ps += a[s][k];
        #pragma unroll
        for (int o = 16; o; o >>= 1) ps += __shfl_xor_sync(0xffffffffu, ps, o);
        float mu = ps * (1.f / 384.f);
        float pv = 0.f;
        for (int k = lane; k < 384; k += 32) {
            float d = a[s][k] - mu;
            pv += d * d;
        }
        #pragma unroll
        for (int o = 16; o; o >>= 1) pv += __shfl_xor_sync(0xffffffffu, pv, o);
        float rstd = rsqrtf(pv * (1.f / 384.f) + 1e-5f);
        for (int k = lane; k < 384; k += 32) {
            float xn = (a[s][k] - mu) * rstd * gamma[k] + beta[k];
            a[s][k] = xn / (1.f + __expf(-xn));   // silu
        }
    }
    __syncthreads();

    int j = tid & 127;
    int half = tid >> 7;
    int k0 = half * 192;
    float r[16];
    #pragma unroll
    for (int s = 0; s < 16; ++s) r[s] = 0.f;

    const float* W1h = W1 + k0 * H + j;
    for (int kg = 0; kg < 48; ++kg) {
        float w0 = W1h[(kg * 4 + 0) * H];
        float w1 = W1h[(kg * 4 + 1) * H];
        float w2 = W1h[(kg * 4 + 2) * H];
        float w3 = W1h[(kg * 4 + 3) * H];
        #pragma unroll
        for (int s = 0; s < 16; ++s) {
            float4 av = reinterpret_cast<const float4*>(&a[s][k0])[kg];
            r[s] += av.x * w0 + av.y * w1 + av.z * w2 + av.w * w3;
        }
    }

    if (half == 1) {
        #pragma unroll
        for (int s = 0; s < 16; ++s) rh[s][j] = r[s];
    }
    __syncthreads();
    if (half == 0) {
        float b1j = b1f[j];
        float w2j = W2[j];
        #pragma unroll
        for (int s = 0; s < 16; ++s) {
            float x = r[s] + rh[s][j] + b1j;
            x = x / (1.f + __expf(-x));           // silu
            rh[s][j] = x * w2j;
        }
    }
    __syncthreads();

    // reduce 128 cols per row -> scalar
    for (int s = wid; s < 16; s += 8) {
        float p = rh[s][lane] + rh[s][lane + 32] + rh[s][lane + 64] + rh[s][lane + 96];
        #pragma unroll
        for (int o = 16; o; o >>= 1) p += __shfl_xor_sync(0xffffffffu, p, o);
        if (lane == 0) out[seg0 + s] = p + b2f[0];
    }
}

// ---------------- launch ----------------
extern "C" void kernel_launch(void* const* d_in, const int* in_sizes, int n_in,
                              void* d_out, int out_size) {
    const float* h0  = (const float*)d_in[0];
    const float* h1  = (const float*)d_in[1];
    const float* h2  = (const float*)d_in[2];
    const int*   b0  = (const int*)d_in[3];
    const int*   b1  = (const int*)d_in[4];
    const int*   b2  = (const int*)d_in[5];
    const float* Wg0 = (const float*)d_in[6];
    const float* bg0 = (const float*)d_in[7];
    const float* Wg1 = (const float*)d_in[8];
    const float* bg1 = (const float*)d_in[9];
    const float* Wg2 = (const float*)d_in[10];
    const float* bg2 = (const float*)d_in[11];
    const float* Wp0 = (const float*)d_in[12];
    const float* bp0 = (const float*)d_in[13];
    const float* Wp1 = (const float*)d_in[14];
    const float* bp1 = (const float*)d_in[15];
    const float* Wp2 = (const float*)d_in[16];
    const float* bp2 = (const float*)d_in[17];
    const float* gamma = (const float*)d_in[18];
    const float* beta  = (const float*)d_in[19];
    const float* W1  = (const float*)d_in[20];
    const float* b1f = (const float*)d_in[21];
    const float* W2  = (const float*)d_in[22];
    const float* b2f = (const float*)d_in[23];

    int N0 = in_sizes[3];
    int N1 = in_sizes[4];
    int N2 = in_sizes[5];

    init_kernel<<<384, 256>>>();

    int npw0 = (N0 + POOL_WARPS - 1) / POOL_WARPS;
    int npw1 = (N1 + POOL_WARPS - 1) / POOL_WARPS;
    int npw2 = (N2 + POOL_WARPS - 1) / POOL_WARPS;
    pool_kernel<<<POOL_BLOCKS, POOL_THREADS>>>(h0, b0, Wg0, bg0, N0, 0, npw0);
    pool_kernel<<<POOL_BLOCKS, POOL_THREADS>>>(h1, b1, Wg1, bg1, N1, 1, npw1);
    pool_kernel<<<POOL_BLOCKS, POOL_THREADS>>>(h2, b2, Wg2, bg2, N2, 2, npw2);

    dim3 gp(B / 16, RANKS);
    proj_kernel<<<gp, 256>>>(Wp0, bp0, Wp1, bp1, Wp2, bp2);

    final_kernel<<<B / 16, 256>>>(gamma, beta, W1, b1f, W2, b2f, (float*)d_out);
}

// round 3
// speedup vs baseline: 1.6022x; 1.6022x over previous
#include <cuda_runtime.h>
#include <math.h>

#define H 128
#define B 512
#define RANKS 3
#define POOL_BLOCKS_X 512
#define POOL_THREADS 256
#define POOL_WARPS_PER_RANK (POOL_BLOCKS_X * POOL_THREADS / 32)

// ---------------- scratch (no allocations allowed) ----------------
__device__ float g_sum [RANKS][B * H];
__device__ float g_gsum[RANKS][B * H];
__device__ float g_max [RANKS][B * H];
__device__ float g_cnt [RANKS][B];
__device__ float g_state[B][3 * H];

__device__ __forceinline__ void atomicMaxF(float* addr, float v) {
    if (v >= 0.f) atomicMax((int*)addr, __float_as_int(v));
    else          atomicMin((unsigned int*)addr, __float_as_uint(v));
}

// ---------------- init: reset accumulators every replay ----------------
__global__ void init_kernel() {
    int i = blockIdx.x * blockDim.x + threadIdx.x;
    int stride = gridDim.x * blockDim.x;
    int tot = RANKS * B * H;
    for (int idx = i; idx < tot; idx += stride) {
        int r = idx / (B * H);
        int o = idx - r * (B * H);
        g_sum[r][o]  = 0.f;
        g_gsum[r][o] = 0.f;
        g_max[r][o]  = -INFINITY;
    }
    if (i < RANKS * B) g_cnt[i / B][i % B] = 0.f;
}

// ---------------- stage 1: fused gated multi-agg pooling (all 3 ranks) ----
// blockIdx.y = rank. One warp per contiguous node strip; lane owns 4 columns.
// Fast path: 4 nodes per iteration (4 independent streaming float4 loads ->
// MLP=4) when all 4 stay in the current segment. Scalar path at boundaries.
__global__ void __launch_bounds__(POOL_THREADS)
pool_kernel(const float* __restrict__ h0, const float* __restrict__ h1,
            const float* __restrict__ h2,
            const int* __restrict__ bb0, const int* __restrict__ bb1,
            const int* __restrict__ bb2,
            const float* __restrict__ Wg0, const float* __restrict__ Wg1,
            const float* __restrict__ Wg2,
            const float* __restrict__ bgp0, const float* __restrict__ bgp1,
            const float* __restrict__ bgp2,
            int N0, int N1, int N2) {
    int rank = blockIdx.y;
    const float* __restrict__ h  = (rank == 0) ? h0  : (rank == 1) ? h1  : h2;
    const int*   __restrict__ b  = (rank == 0) ? bb0 : (rank == 1) ? bb1 : bb2;
    const float* __restrict__ Wg = (rank == 0) ? Wg0 : (rank == 1) ? Wg1 : Wg2;
    const float* __restrict__ bg = (rank == 0) ? bgp0 : (rank == 1) ? bgp1 : bgp2;
    int N = (rank == 0) ? N0 : (rank == 1) ? N1 : N2;

    int npw = (N + POOL_WARPS_PER_RANK - 1) / POOL_WARPS_PER_RANK;
    int gwid = (blockIdx.x * blockDim.x + threadIdx.x) >> 5;
    int lane = threadIdx.x & 31;
    int start = gwid * npw;
    if (start >= N) return;
    int end = min(N, start + npw);

    float4 wg = reinterpret_cast<const float4*>(Wg)[lane];
    float bgv = bg[0];

    float* __restrict__ sums  = g_sum[rank];
    float* __restrict__ gsums = g_gsum[rank];
    float* __restrict__ maxs  = g_max[rank];
    float* __restrict__ cnts  = g_cnt[rank];

    const float4* __restrict__ h4 = reinterpret_cast<const float4*>(h);

    int cur = b[start];
    float4 s4  = make_float4(0.f, 0.f, 0.f, 0.f);
    float4 gs4 = make_float4(0.f, 0.f, 0.f, 0.f);
    float4 m4  = make_float4(-INFINITY, -INFINITY, -INFINITY, -INFINITY);
    float  c   = 0.f;

    auto flush = [&]() {
        int base = cur * H + (lane << 2);
        atomicAdd(&sums[base + 0], s4.x);
        atomicAdd(&sums[base + 1], s4.y);
        atomicAdd(&sums[base + 2], s4.z);
        atomicAdd(&sums[base + 3], s4.w);
        atomicAdd(&gsums[base + 0], gs4.x);
        atomicAdd(&gsums[base + 1], gs4.y);
        atomicAdd(&gsums[base + 2], gs4.z);
        atomicAdd(&gsums[base + 3], gs4.w);
        atomicMaxF(&maxs[base + 0], m4.x);
        atomicMaxF(&maxs[base + 1], m4.y);
        atomicMaxF(&maxs[base + 2], m4.z);
        atomicMaxF(&maxs[base + 3], m4.w);
        if (lane == 0) atomicAdd(&cnts[cur], c);
    };

    auto acc1 = [&](const float4& v, float g) {
        s4.x += v.x;  s4.y += v.y;  s4.z += v.z;  s4.w += v.w;
        m4.x = fmaxf(m4.x, v.x);  m4.y = fmaxf(m4.y, v.y);
        m4.z = fmaxf(m4.z, v.z);  m4.w = fmaxf(m4.w, v.w);
        gs4.x += g * v.x;  gs4.y += g * v.y;
        gs4.z += g * v.z;  gs4.w += g * v.w;
        c += 1.f;
    };

    int n = start;
    while (n < end) {
        if (n + 4 <= end) {
            int sA = b[n], sB = b[n + 1], sC = b[n + 2], sD = b[n + 3];
            if ((sA == cur) & (sB == cur) & (sC == cur) & (sD == cur)) {
                // fast path: 4 independent streaming loads (MLP=4)
                float4 v0 = __ldcs(&h4[(n + 0) * 32 + lane]);
                float4 v1 = __ldcs(&h4[(n + 1) * 32 + lane]);
                float4 v2 = __ldcs(&h4[(n + 2) * 32 + lane]);
                float4 v3 = __ldcs(&h4[(n + 3) * 32 + lane]);
                float p0 = v0.x * wg.x + v0.y * wg.y + v0.z * wg.z + v0.w * wg.w;
                float p1 = v1.x * wg.x + v1.y * wg.y + v1.z * wg.z + v1.w * wg.w;
                float p2 = v2.x * wg.x + v2.y * wg.y + v2.z * wg.z + v2.w * wg.w;
                float p3 = v3.x * wg.x + v3.y * wg.y + v3.z * wg.z + v3.w * wg.w;
                #pragma unroll
                for (int o = 16; o; o >>= 1) {
                    p0 += __shfl_xor_sync(0xffffffffu, p0, o);
                    p1 += __shfl_xor_sync(0xffffffffu, p1, o);
                    p2 += __shfl_xor_sync(0xffffffffu, p2, o);
                    p3 += __shfl_xor_sync(0xffffffffu, p3, o);
                }
                float g0 = 1.f / (1.f + __expf(-(p0 + bgv)));
                float g1 = 1.f / (1.f + __expf(-(p1 + bgv)));
                float g2 = 1.f / (1.f + __expf(-(p2 + bgv)));
                float g3 = 1.f / (1.f + __expf(-(p3 + bgv)));
                acc1(v0, g0); acc1(v1, g1); acc1(v2, g2); acc1(v3, g3);
                n += 4;
                continue;
            }
        }
        // scalar path (segment boundary or tail)
        int seg = b[n];
        float4 v = __ldcs(&h4[n * 32 + lane]);
        if (seg != cur) {
            flush();
            s4  = make_float4(0.f, 0.f, 0.f, 0.f);
            gs4 = make_float4(0.f, 0.f, 0.f, 0.f);
            m4  = make_float4(-INFINITY, -INFINITY, -INFINITY, -INFINITY);
            c   = 0.f;
            cur = seg;
        }
        float p = v.x * wg.x + v.y * wg.y + v.z * wg.z + v.w * wg.w;
        #pragma unroll
        for (int o = 16; o; o >>= 1) p += __shfl_xor_sync(0xffffffffu, p, o);
        float g = 1.f / (1.f + __expf(-(p + bgv)));
        acc1(v, g);
        ++n;
    }
    flush();
}

// ---------------- stage 2: [B,4H] @ Wp[4H,H] + bp -> state slice ----------------
// grid: (B/16, 3 ranks), 256 threads (128 output cols x 2 K-halves)
__global__ void proj_kernel(const float* __restrict__ Wp0, const float* __restrict__ bp0,
                            const float* __restrict__ Wp1, const float* __restrict__ bp1,
                            const float* __restrict__ Wp2, const float* __restrict__ bp2) {
    int rank = blockIdx.y;
    const float* Wp = (rank == 0) ? Wp0 : (rank == 1) ? Wp1 : Wp2;
    const float* bp = (rank == 0) ? bp0 : (rank == 1) ? bp1 : bp2;
    int seg0 = blockIdx.x * 16;
    int tid = threadIdx.x;

    __shared__ float a[16][512];    // agg tile, k-major
    __shared__ float cs[16];
    __shared__ float rh[16][128];

    const float* __restrict__ sums  = g_sum[rank];
    const float* __restrict__ gsums = g_gsum[rank];
    const float* __restrict__ maxs  = g_max[rank];

    if (tid < 16) cs[tid] = g_cnt[rank][seg0 + tid];
    __syncthreads();

    for (int idx = tid; idx < 16 * 512; idx += 256) {
        int s = idx >> 9;
        int k = idx & 511;
        int seg = seg0 + s;
        float v;
        if (k < 128)      v = sums[seg * H + k];
        else if (k < 256) v = sums[seg * H + (k - 128)] / fmaxf(cs[s], 1.f);
        else if (k < 384) v = (cs[s] > 0.f) ? maxs[seg * H + (k - 256)] : 0.f;
        else              v = gsums[seg * H + (k - 384)];
        a[s][k] = v;
    }
    __syncthreads();

    int j = tid & 127;
    int half = tid >> 7;
    int k0 = half * 256;
    float r[16];
    #pragma unroll
    for (int s = 0; s < 16; ++s) r[s] = 0.f;

    const float* Wph = Wp + k0 * H + j;
    for (int kg = 0; kg < 64; ++kg) {
        float w0 = Wph[(kg * 4 + 0) * H];
        float w1 = Wph[(kg * 4 + 1) * H];
        float w2 = Wph[(kg * 4 + 2) * H];
        float w3 = Wph[(kg * 4 + 3) * H];
        #pragma unroll
        for (int s = 0; s < 16; ++s) {
            float4 av = reinterpret_cast<const float4*>(&a[s][k0])[kg];
            r[s] += av.x * w0 + av.y * w1 + av.z * w2 + av.w * w3;
        }
    }

    if (half == 1) {
        #pragma unroll
        for (int s = 0; s < 16; ++s) rh[s][j] = r[s];
    }
    __syncthreads();
    if (half == 0) {
        float bpj = bp[j];
        #pragma unroll
        for (int s = 0; s < 16; ++s)
            g_state[seg0 + s][rank * H + j] = r[s] + rh[s][j] + bpj;
    }
}

// ---------------- stage 3: LN + SiLU + MLP + final dot ----------------
// grid: B/16 blocks, 256 threads
__global__ void final_kernel(const float* __restrict__ gamma, const float* __restrict__ beta,
                             const float* __restrict__ W1,    const float* __restrict__ b1f,
                             const float* __restrict__ W2,    const float* __restrict__ b2f,
                             float* __restrict__ out) {
    int seg0 = blockIdx.x * 16;
    int tid = threadIdx.x;
    int wid = tid >> 5;
    int lane = tid & 31;

    __shared__ float a[16][384];
    __shared__ float rh[16][128];

    for (int idx = tid; idx < 16 * 384; idx += 256) {
        int s = idx / 384;
        int k = idx - s * 384;
        a[s][k] = g_state[seg0 + s][k];
    }
    __syncthreads();

    // per-row LayerNorm + SiLU, warp handles rows wid, wid+8
    for (int s = wid; s < 16; s += 8) {
        float ps = 0.f;
        for (int k = lane; k < 384; k += 32) ps += a[s][k];
        #pragma unroll
        for (int o = 16; o; o >>= 1) ps += __shfl_xor_sync(0xffffffffu, ps, o);
        float mu = ps * (1.f / 384.f);
        float pv = 0.f;
        for (int k = lane; k < 384; k += 32) {
            float d = a[s][k] - mu;
            pv += d * d;
        }
        #pragma unroll
        for (int o = 16; o; o >>= 1) pv += __shfl_xor_sync(0xffffffffu, pv, o);
        float rstd = rsqrtf(pv * (1.f / 384.f) + 1e-5f);
        for (int k = lane; k < 384; k += 32) {
            float xn = (a[s][k] - mu) * rstd * gamma[k] + beta[k];
            a[s][k] = xn / (1.f + __expf(-xn));   // silu
        }
    }
    __syncthreads();

    int j = tid & 127;
    int half = tid >> 7;
    int k0 = half * 192;
    float r[16];
    #pragma unroll
    for (int s = 0; s < 16; ++s) r[s] = 0.f;

    const float* W1h = W1 + k0 * H + j;
    for (int kg = 0; kg < 48; ++kg) {
        float w0 = W1h[(kg * 4 + 0) * H];
        float w1 = W1h[(kg * 4 + 1) * H];
        float w2 = W1h[(kg * 4 + 2) * H];
        float w3 = W1h[(kg * 4 + 3) * H];
        #pragma unroll
        for (int s = 0; s < 16; ++s) {
            float4 av = reinterpret_cast<const float4*>(&a[s][k0])[kg];
            r[s] += av.x * w0 + av.y * w1 + av.z * w2 + av.w * w3;
        }
    }

    if (half == 1) {
        #pragma unroll
        for (int s = 0; s < 16; ++s) rh[s][j] = r[s];
    }
    __syncthreads();
    if (half == 0) {
        float b1j = b1f[j];
        float w2j = W2[j];
        #pragma unroll
        for (int s = 0; s < 16; ++s) {
            float x = r[s] + rh[s][j] + b1j;
            x = x / (1.f + __expf(-x));           // silu
            rh[s][j] = x * w2j;
        }
    }
    __syncthreads();

    // reduce 128 cols per row -> scalar
    for (int s = wid; s < 16; s += 8) {
        float p = rh[s][lane] + rh[s][lane + 32] + rh[s][lane + 64] + rh[s][lane + 96];
        #pragma unroll
        for (int o = 16; o; o >>= 1) p += __shfl_xor_sync(0xffffffffu, p, o);
        if (lane == 0) out[seg0 + s] = p + b2f[0];
    }
}

// ---------------- launch ----------------
extern "C" void kernel_launch(void* const* d_in, const int* in_sizes, int n_in,
                              void* d_out, int out_size) {
    const float* h0  = (const float*)d_in[0];
    const float* h1  = (const float*)d_in[1];
    const float* h2  = (const float*)d_in[2];
    const int*   b0  = (const int*)d_in[3];
    const int*   b1  = (const int*)d_in[4];
    const int*   b2  = (const int*)d_in[5];
    const float* Wg0 = (const float*)d_in[6];
    const float* bg0 = (const float*)d_in[7];
    const float* Wg1 = (const float*)d_in[8];
    const float* bg1 = (const float*)d_in[9];
    const float* Wg2 = (const float*)d_in[10];
    const float* bg2 = (const float*)d_in[11];
    const float* Wp0 = (const float*)d_in[12];
    const float* bp0 = (const float*)d_in[13];
    const float* Wp1 = (const float*)d_in[14];
    const float* bp1 = (const float*)d_in[15];
    const float* Wp2 = (const float*)d_in[16];
    const float* bp2 = (const float*)d_in[17];
    const float* gamma = (const float*)d_in[18];
    const float* beta  = (const float*)d_in[19];
    const float* W1  = (const float*)d_in[20];
    const float* b1f = (const float*)d_in[21];
    const float* W2  = (const float*)d_in[22];
    const float* b2f = (const float*)d_in[23];

    int N0 = in_sizes[3];
    int N1 = in_sizes[4];
    int N2 = in_sizes[5];

    init_kernel<<<384, 256>>>();

    dim3 gpool(POOL_BLOCKS_X, RANKS);
    pool_kernel<<<gpool, POOL_THREADS>>>(h0, h1, h2, b0, b1, b2,
                                         Wg0, Wg1, Wg2, bg0, bg1, bg2,
                                         N0, N1, N2);

    dim3 gp(B / 16, RANKS);
    proj_kernel<<<gp, 256>>>(Wp0, bp0, Wp1, bp1, Wp2, bp2);

    final_kernel<<<B / 16, 256>>>(gamma, beta, W1, b1f, W2, b2f, (float*)d_out);
}

// round 4
// speedup vs baseline: 2.0710x; 1.2926x over previous
#include <cuda_runtime.h>
#include <math.h>

#define H 128
#define B 512
#define RANKS 3
#define POOL_BLOCKS_X 512
#define POOL_THREADS 256
#define POOL_WARPS_PER_RANK (POOL_BLOCKS_X * POOL_THREADS / 32)

// ---------------- scratch (no allocations allowed) ----------------
__device__ float g_sum [RANKS][B * H];
__device__ float g_gsum[RANKS][B * H];
__device__ float g_max [RANKS][B * H];
__device__ float g_cnt [RANKS][B];
__device__ float g_state[B][3 * H];

__device__ __forceinline__ void atomicMaxF(float* addr, float v) {
    if (v >= 0.f) atomicMax((int*)addr, __float_as_int(v));
    else          atomicMin((unsigned int*)addr, __float_as_uint(v));
}

// ---------------- init: reset accumulators every replay ----------------
__global__ void init_kernel() {
    int i = blockIdx.x * blockDim.x + threadIdx.x;
    int stride = gridDim.x * blockDim.x;
    int tot = RANKS * B * H;
    for (int idx = i; idx < tot; idx += stride) {
        int r = idx / (B * H);
        int o = idx - r * (B * H);
        g_sum[r][o]  = 0.f;
        g_gsum[r][o] = 0.f;
        g_max[r][o]  = -INFINITY;
    }
    if (i < RANKS * B) g_cnt[i / B][i % B] = 0.f;
}

// ---------------- stage 1: fused gated multi-agg pooling (all 3 ranks) ----
// blockIdx.y = rank. One warp per contiguous node strip; lane owns 4 columns.
// Fast path: 8 nodes per iteration (8 independent streaming float4 loads ->
// MLP=8) when all 8 stay in the current segment. Scalar path at boundaries.
__global__ void __launch_bounds__(POOL_THREADS)
pool_kernel(const float* __restrict__ h0, const float* __restrict__ h1,
            const float* __restrict__ h2,
            const int* __restrict__ bb0, const int* __restrict__ bb1,
            const int* __restrict__ bb2,
            const float* __restrict__ Wg0, const float* __restrict__ Wg1,
            const float* __restrict__ Wg2,
            const float* __restrict__ bgp0, const float* __restrict__ bgp1,
            const float* __restrict__ bgp2,
            int N0, int N1, int N2) {
    int rank = blockIdx.y;
    const float* __restrict__ h  = (rank == 0) ? h0  : (rank == 1) ? h1  : h2;
    const int*   __restrict__ b  = (rank == 0) ? bb0 : (rank == 1) ? bb1 : bb2;
    const float* __restrict__ Wg = (rank == 0) ? Wg0 : (rank == 1) ? Wg1 : Wg2;
    const float* __restrict__ bg = (rank == 0) ? bgp0 : (rank == 1) ? bgp1 : bgp2;
    int N = (rank == 0) ? N0 : (rank == 1) ? N1 : N2;

    int npw = (N + POOL_WARPS_PER_RANK - 1) / POOL_WARPS_PER_RANK;
    int gwid = (blockIdx.x * blockDim.x + threadIdx.x) >> 5;
    int lane = threadIdx.x & 31;
    int start = gwid * npw;
    if (start >= N) return;
    int end = min(N, start + npw);

    float4 wg = reinterpret_cast<const float4*>(Wg)[lane];
    float bgv = bg[0];

    float* __restrict__ sums  = g_sum[rank];
    float* __restrict__ gsums = g_gsum[rank];
    float* __restrict__ maxs  = g_max[rank];
    float* __restrict__ cnts  = g_cnt[rank];

    const float4* __restrict__ h4 = reinterpret_cast<const float4*>(h);

    int cur = b[start];
    float4 s4  = make_float4(0.f, 0.f, 0.f, 0.f);
    float4 gs4 = make_float4(0.f, 0.f, 0.f, 0.f);
    float4 m4  = make_float4(-INFINITY, -INFINITY, -INFINITY, -INFINITY);
    float  c   = 0.f;

    auto flush = [&]() {
        int base = cur * H + (lane << 2);
        atomicAdd(&sums[base + 0], s4.x);
        atomicAdd(&sums[base + 1], s4.y);
        atomicAdd(&sums[base + 2], s4.z);
        atomicAdd(&sums[base + 3], s4.w);
        atomicAdd(&gsums[base + 0], gs4.x);
        atomicAdd(&gsums[base + 1], gs4.y);
        atomicAdd(&gsums[base + 2], gs4.z);
        atomicAdd(&gsums[base + 3], gs4.w);
        atomicMaxF(&maxs[base + 0], m4.x);
        atomicMaxF(&maxs[base + 1], m4.y);
        atomicMaxF(&maxs[base + 2], m4.z);
        atomicMaxF(&maxs[base + 3], m4.w);
        if (lane == 0) atomicAdd(&cnts[cur], c);
    };

    auto acc1 = [&](const float4& v, float g) {
        s4.x += v.x;  s4.y += v.y;  s4.z += v.z;  s4.w += v.w;
        m4.x = fmaxf(m4.x, v.x);  m4.y = fmaxf(m4.y, v.y);
        m4.z = fmaxf(m4.z, v.z);  m4.w = fmaxf(m4.w, v.w);
        gs4.x += g * v.x;  gs4.y += g * v.y;
        gs4.z += g * v.z;  gs4.w += g * v.w;
        c += 1.f;
    };

    int n = start;
    while (n < end) {
        if (n + 8 <= end) {
            int same = 1;
            #pragma unroll
            for (int u = 0; u < 8; ++u) same &= (b[n + u] == cur);
            if (same) {
                // fast path: 8 independent streaming loads (MLP=8)
                float4 v[8];
                #pragma unroll
                for (int u = 0; u < 8; ++u)
                    v[u] = __ldcs(&h4[(n + u) * 32 + lane]);
                float p[8];
                #pragma unroll
                for (int u = 0; u < 8; ++u)
                    p[u] = v[u].x * wg.x + v[u].y * wg.y + v[u].z * wg.z + v[u].w * wg.w;
                #pragma unroll
                for (int o = 16; o; o >>= 1) {
                    #pragma unroll
                    for (int u = 0; u < 8; ++u)
                        p[u] += __shfl_xor_sync(0xffffffffu, p[u], o);
                }
                #pragma unroll
                for (int u = 0; u < 8; ++u) {
                    float g = 1.f / (1.f + __expf(-(p[u] + bgv)));
                    acc1(v[u], g);
                }
                n += 8;
                continue;
            }
        }
        // scalar path (segment boundary or tail)
        int seg = b[n];
        float4 v = __ldcs(&h4[n * 32 + lane]);
        if (seg != cur) {
            flush();
            s4  = make_float4(0.f, 0.f, 0.f, 0.f);
            gs4 = make_float4(0.f, 0.f, 0.f, 0.f);
            m4  = make_float4(-INFINITY, -INFINITY, -INFINITY, -INFINITY);
            c   = 0.f;
            cur = seg;
        }
        float p = v.x * wg.x + v.y * wg.y + v.z * wg.z + v.w * wg.w;
        #pragma unroll
        for (int o = 16; o; o >>= 1) p += __shfl_xor_sync(0xffffffffu, p, o);
        float g = 1.f / (1.f + __expf(-(p + bgv)));
        acc1(v, g);
        ++n;
    }
    flush();
}

// ---------------- stage 2: [B,4H] @ Wp[4H,H] + bp -> state slice ----------------
// grid: (B/8, 3 ranks), 512 threads: j = tid&127 (output col),
// q = tid>>7 (K-quarter of 128). 8 segments per block, r[8] accumulators.
__global__ void __launch_bounds__(512)
proj_kernel(const float* __restrict__ Wp0, const float* __restrict__ bp0,
            const float* __restrict__ Wp1, const float* __restrict__ bp1,
            const float* __restrict__ Wp2, const float* __restrict__ bp2) {
    int rank = blockIdx.y;
    const float* Wp = (rank == 0) ? Wp0 : (rank == 1) ? Wp1 : Wp2;
    const float* bp = (rank == 0) ? bp0 : (rank == 1) ? bp1 : bp2;
    int seg0 = blockIdx.x * 8;
    int tid = threadIdx.x;

    __shared__ float a[8][512];     // agg tile, k-major
    __shared__ float cs[8];
    __shared__ float rp[3][8][128]; // partials from quarters 1..3

    const float* __restrict__ sums  = g_sum[rank];
    const float* __restrict__ gsums = g_gsum[rank];
    const float* __restrict__ maxs  = g_max[rank];

    if (tid < 8) cs[tid] = g_cnt[rank][seg0 + tid];
    __syncthreads();

    for (int idx = tid; idx < 8 * 512; idx += 512) {
        int s = idx >> 9;
        int k = idx & 511;
        int seg = seg0 + s;
        float v;
        if (k < 128)      v = sums[seg * H + k];
        else if (k < 256) v = sums[seg * H + (k - 128)] / fmaxf(cs[s], 1.f);
        else if (k < 384) v = (cs[s] > 0.f) ? maxs[seg * H + (k - 256)] : 0.f;
        else              v = gsums[seg * H + (k - 384)];
        a[s][k] = v;
    }
    __syncthreads();

    int j = tid & 127;
    int q = tid >> 7;           // 0..3, K-quarter
    int k0 = q * 128;
    float r[8];
    #pragma unroll
    for (int s = 0; s < 8; ++s) r[s] = 0.f;

    const float* Wph = Wp + k0 * H + j;
    for (int kg = 0; kg < 32; ++kg) {
        float w0 = Wph[(kg * 4 + 0) * H];
        float w1 = Wph[(kg * 4 + 1) * H];
        float w2 = Wph[(kg * 4 + 2) * H];
        float w3 = Wph[(kg * 4 + 3) * H];
        #pragma unroll
        for (int s = 0; s < 8; ++s) {
            float4 av = reinterpret_cast<const float4*>(&a[s][k0])[kg];
            r[s] += av.x * w0 + av.y * w1 + av.z * w2 + av.w * w3;
        }
    }

    if (q > 0) {
        #pragma unroll
        for (int s = 0; s < 8; ++s) rp[q - 1][s][j] = r[s];
    }
    __syncthreads();
    if (q == 0) {
        float bpj = bp[j];
        #pragma unroll
        for (int s = 0; s < 8; ++s)
            g_state[seg0 + s][rank * H + j] =
                r[s] + rp[0][s][j] + rp[1][s][j] + rp[2][s][j] + bpj;
    }
}

// ---------------- stage 3: LN + SiLU + MLP + final dot ----------------
// grid: B/4 blocks, 512 threads: j = tid&127, q = tid>>7 (K-range of 96).
__global__ void __launch_bounds__(512)
final_kernel(const float* __restrict__ gamma, const float* __restrict__ beta,
             const float* __restrict__ W1,    const float* __restrict__ b1f,
             const float* __restrict__ W2,    const float* __restrict__ b2f,
             float* __restrict__ out) {
    int seg0 = blockIdx.x * 4;
    int tid = threadIdx.x;
    int wid = tid >> 5;
    int lane = tid & 31;

    __shared__ float a[4][384];
    __shared__ float rp[3][4][128];
    __shared__ float fo[4][128];

    for (int idx = tid; idx < 4 * 384; idx += 512) {
        int s = idx / 384;
        int k = idx - s * 384;
        a[s][k] = g_state[seg0 + s][k];
    }
    __syncthreads();

    // per-row LayerNorm + SiLU: warp s handles row s (s < 4)
    if (wid < 4) {
        int s = wid;
        float ps = 0.f;
        #pragma unroll
        for (int kk = 0; kk < 12; ++kk) ps += a[s][lane + kk * 32];
        #pragma unroll
        for (int o = 16; o; o >>= 1) ps += __shfl_xor_sync(0xffffffffu, ps, o);
        float mu = ps * (1.f / 384.f);
        float pv = 0.f;
        #pragma unroll
        for (int kk = 0; kk < 12; ++kk) {
            float d = a[s][lane + kk * 32] - mu;
            pv += d * d;
        }
        #pragma unroll
        for (int o = 16; o; o >>= 1) pv += __shfl_xor_sync(0xffffffffu, pv, o);
        float rstd = rsqrtf(pv * (1.f / 384.f) + 1e-5f);
        #pragma unroll
        for (int kk = 0; kk < 12; ++kk) {
            int k = lane + kk * 32;
            float xn = (a[s][k] - mu) * rstd * gamma[k] + beta[k];
            a[s][k] = xn / (1.f + __expf(-xn));   // silu
        }
    }
    __syncthreads();

    int j = tid & 127;
    int q = tid >> 7;          // 0..3, each covers 96 K values
    int k0 = q * 96;
    float r[4];
    #pragma unroll
    for (int s = 0; s < 4; ++s) r[s] = 0.f;

    const float* W1h = W1 + k0 * H + j;
    for (int kg = 0; kg < 24; ++kg) {
        float w0 = W1h[(kg * 4 + 0) * H];
        float w1 = W1h[(kg * 4 + 1) * H];
        float w2 = W1h[(kg * 4 + 2) * H];
        float w3 = W1h[(kg * 4 + 3) * H];
        #pragma unroll
        for (int s = 0; s < 4; ++s) {
            float4 av = reinterpret_cast<const float4*>(&a[s][k0])[kg];
            r[s] += av.x * w0 + av.y * w1 + av.z * w2 + av.w * w3;
        }
    }

    if (q > 0) {
        #pragma unroll
        for (int s = 0; s < 4; ++s) rp[q - 1][s][j] = r[s];
    }
    __syncthreads();
    if (q == 0) {
        float b1j = b1f[j];
        float w2j = W2[j];
        #pragma unroll
        for (int s = 0; s < 4; ++s) {
            float x = r[s] + rp[0][s][j] + rp[1][s][j] + rp[2][s][j] + b1j;
            x = x / (1.f + __expf(-x));           // silu
            fo[s][j] = x * w2j;
        }
    }
    __syncthreads();

    // reduce 128 cols per row -> scalar (warp s reduces row s)
    if (wid < 4) {
        int s = wid;
        float p = fo[s][lane] + fo[s][lane + 32] + fo[s][lane + 64] + fo[s][lane + 96];
        #pragma unroll
        for (int o = 16; o; o >>= 1) p += __shfl_xor_sync(0xffffffffu, p, o);
        if (lane == 0) out[seg0 + s] = p + b2f[0];
    }
}

// ---------------- launch ----------------
extern "C" void kernel_launch(void* const* d_in, const int* in_sizes, int n_in,
                              void* d_out, int out_size) {
    const float* h0  = (const float*)d_in[0];
    const float* h1  = (const float*)d_in[1];
    const float* h2  = (const float*)d_in[2];
    const int*   b0  = (const int*)d_in[3];
    const int*   b1  = (const int*)d_in[4];
    const int*   b2  = (const int*)d_in[5];
    const float* Wg0 = (const float*)d_in[6];
    const float* bg0 = (const float*)d_in[7];
    const float* Wg1 = (const float*)d_in[8];
    const float* bg1 = (const float*)d_in[9];
    const float* Wg2 = (const float*)d_in[10];
    const float* bg2 = (const float*)d_in[11];
    const float* Wp0 = (const float*)d_in[12];
    const float* bp0 = (const float*)d_in[13];
    const float* Wp1 = (const float*)d_in[14];
    const float* bp1 = (const float*)d_in[15];
    const float* Wp2 = (const float*)d_in[16];
    const float* bp2 = (const float*)d_in[17];
    const float* gamma = (const float*)d_in[18];
    const float* beta  = (const float*)d_in[19];
    const float* W1  = (const float*)d_in[20];
    const float* b1f = (const float*)d_in[21];
    const float* W2  = (const float*)d_in[22];
    const float* b2f = (const float*)d_in[23];

    int N0 = in_sizes[3];
    int N1 = in_sizes[4];
    int N2 = in_sizes[5];

    init_kernel<<<384, 256>>>();

    dim3 gpool(POOL_BLOCKS_X, RANKS);
    pool_kernel<<<gpool, POOL_THREADS>>>(h0, h1, h2, b0, b1, b2,
                                         Wg0, Wg1, Wg2, bg0, bg1, bg2,
                                         N0, N1, N2);

    dim3 gp(B / 8, RANKS);
    proj_kernel<<<gp, 512>>>(Wp0, bp0, Wp1, bp1, Wp2, bp2);

    final_kernel<<<B / 4, 512>>>(gamma, beta, W1, b1f, W2, b2f, (float*)d_out);
}

// round 8
// speedup vs baseline: 2.0901x; 1.0092x over previous
#include <cuda_runtime.h>
#include <math.h>

#define H 128
#define B 512
#define RANKS 3
#define POOL_BLOCKS_X 512
#define POOL_THREADS 256
#define POOL_WARPS_PER_RANK (POOL_BLOCKS_X * POOL_THREADS / 32)

// ---------------- scratch (no allocations allowed) ----------------
__device__ float g_sum [RANKS][B * H];
__device__ float g_gsum[RANKS][B * H];
__device__ float g_max [RANKS][B * H];
__device__ float g_cnt [RANKS][B];
__device__ float g_state[B][3 * H];

__device__ __forceinline__ void atomicMaxF(float* addr, float v) {
    if (v >= 0.f) atomicMax((int*)addr, __float_as_int(v));
    else          atomicMin((unsigned int*)addr, __float_as_uint(v));
}

// ---------------- init: reset accumulators every replay ----------------
__global__ void init_kernel() {
    int i = blockIdx.x * blockDim.x + threadIdx.x;
    int stride = gridDim.x * blockDim.x;
    int tot = RANKS * B * H;
    for (int idx = i; idx < tot; idx += stride) {
        int r = idx / (B * H);
        int o = idx - r * (B * H);
        g_sum[r][o]  = 0.f;
        g_gsum[r][o] = 0.f;
        g_max[r][o]  = -INFINITY;
    }
    if (i < RANKS * B) g_cnt[i / B][i % B] = 0.f;
}

// ---------------- stage 1: fused gated multi-agg pooling (all 3 ranks) ----
__global__ void __launch_bounds__(POOL_THREADS)
pool_kernel(const float* __restrict__ h0, const float* __restrict__ h1,
            const float* __restrict__ h2,
            const int* __restrict__ bb0, const int* __restrict__ bb1,
            const int* __restrict__ bb2,
            const float* __restrict__ Wg0, const float* __restrict__ Wg1,
            const float* __restrict__ Wg2,
            const float* __restrict__ bgp0, const float* __restrict__ bgp1,
            const float* __restrict__ bgp2,
            int N0, int N1, int N2) {
    int rank = blockIdx.y;
    const float* __restrict__ h  = (rank == 0) ? h0  : (rank == 1) ? h1  : h2;
    const int*   __restrict__ b  = (rank == 0) ? bb0 : (rank == 1) ? bb1 : bb2;
    const float* __restrict__ Wg = (rank == 0) ? Wg0 : (rank == 1) ? Wg1 : Wg2;
    const float* __restrict__ bg = (rank == 0) ? bgp0 : (rank == 1) ? bgp1 : bgp2;
    int N = (rank == 0) ? N0 : (rank == 1) ? N1 : N2;

    int npw = (N + POOL_WARPS_PER_RANK - 1) / POOL_WARPS_PER_RANK;
    int gwid = (blockIdx.x * blockDim.x + threadIdx.x) >> 5;
    int lane = threadIdx.x & 31;
    int start = gwid * npw;
    if (start >= N) return;
    int end = min(N, start + npw);

    float4 wg = reinterpret_cast<const float4*>(Wg)[lane];
    float bgv = bg[0];

    float* __restrict__ sums  = g_sum[rank];
    float* __restrict__ gsums = g_gsum[rank];
    float* __restrict__ maxs  = g_max[rank];
    float* __restrict__ cnts  = g_cnt[rank];

    const float4* __restrict__ h4 = reinterpret_cast<const float4*>(h);

    int cur = b[start];
    float4 s4  = make_float4(0.f, 0.f, 0.f, 0.f);
    float4 gs4 = make_float4(0.f, 0.f, 0.f, 0.f);
    float4 m4  = make_float4(-INFINITY, -INFINITY, -INFINITY, -INFINITY);
    float  c   = 0.f;

    auto flush = [&]() {
        int base = cur * H + (lane << 2);
        atomicAdd(&sums[base + 0], s4.x);
        atomicAdd(&sums[base + 1], s4.y);
        atomicAdd(&sums[base + 2], s4.z);
        atomicAdd(&sums[base + 3], s4.w);
        atomicAdd(&gsums[base + 0], gs4.x);
        atomicAdd(&gsums[base + 1], gs4.y);
        atomicAdd(&gsums[base + 2], gs4.z);
        atomicAdd(&gsums[base + 3], gs4.w);
        atomicMaxF(&maxs[base + 0], m4.x);
        atomicMaxF(&maxs[base + 1], m4.y);
        atomicMaxF(&maxs[base + 2], m4.z);
        atomicMaxF(&maxs[base + 3], m4.w);
        if (lane == 0) atomicAdd(&cnts[cur], c);
    };

    auto acc1 = [&](const float4& v, float g) {
        s4.x += v.x;  s4.y += v.y;  s4.z += v.z;  s4.w += v.w;
        m4.x = fmaxf(m4.x, v.x);  m4.y = fmaxf(m4.y, v.y);
        m4.z = fmaxf(m4.z, v.z);  m4.w = fmaxf(m4.w, v.w);
        gs4.x += g * v.x;  gs4.y += g * v.y;
        gs4.z += g * v.z;  gs4.w += g * v.w;
        c += 1.f;
    };

    int n = start;
    while (n < end) {
        if (n + 8 <= end) {
            int same = 1;
            #pragma unroll
            for (int u = 0; u < 8; ++u) same &= (b[n + u] == cur);
            if (same) {
                float4 v[8];
                #pragma unroll
                for (int u = 0; u < 8; ++u)
                    v[u] = __ldcs(&h4[(n + u) * 32 + lane]);
                float p[8];
                #pragma unroll
                for (int u = 0; u < 8; ++u)
                    p[u] = v[u].x * wg.x + v[u].y * wg.y + v[u].z * wg.z + v[u].w * wg.w;
                #pragma unroll
                for (int o = 16; o; o >>= 1) {
                    #pragma unroll
                    for (int u = 0; u < 8; ++u)
                        p[u] += __shfl_xor_sync(0xffffffffu, p[u], o);
                }
                #pragma unroll
                for (int u = 0; u < 8; ++u) {
                    float g = 1.f / (1.f + __expf(-(p[u] + bgv)));
                    acc1(v[u], g);
                }
                n += 8;
                continue;
            }
        }
        int seg = b[n];
        float4 v = __ldcs(&h4[n * 32 + lane]);
        if (seg != cur) {
            flush();
            s4  = make_float4(0.f, 0.f, 0.f, 0.f);
            gs4 = make_float4(0.f, 0.f, 0.f, 0.f);
            m4  = make_float4(-INFINITY, -INFINITY, -INFINITY, -INFINITY);
            c   = 0.f;
            cur = seg;
        }
        float p = v.x * wg.x + v.y * wg.y + v.z * wg.z + v.w * wg.w;
        #pragma unroll
        for (int o = 16; o; o >>= 1) p += __shfl_xor_sync(0xffffffffu, p, o);
        float g = 1.f / (1.f + __expf(-(p + bgv)));
        acc1(v, g);
        ++n;
    }
    flush();
}

// ---------------- stage 2: [B,4H] @ Wp[4H,H] + bp -> state slice ----------------
// grid: (B/8, 3), 256 threads. cg = tid&31 owns 4 output cols (float4 weight
// loads, LDG.128). kc = tid>>5 owns a 64-wide K chunk. 8 segs/block.
// Partials for kc=0..6 go to smem; kc==7 warp folds them.
__global__ void proj_kernel(const float* __restrict__ Wp0, const float* __restrict__ bp0,
                            const float* __restrict__ Wp1, const float* __restrict__ bp1,
                            const float* __restrict__ Wp2, const float* __restrict__ bp2) {
    int rank = blockIdx.y;
    const float* Wp = (rank == 0) ? Wp0 : (rank == 1) ? Wp1 : Wp2;
    const float* bp = (rank == 0) ? bp0 : (rank == 1) ? bp1 : bp2;
    int seg0 = blockIdx.x * 8;
    int tid = threadIdx.x;

    __shared__ float a[8][512];      // 16 KB, agg tile k-major
    __shared__ float cs[8];
    __shared__ float rp[7][8][128];  // 28 KB partials (kc 0..6)

    const float* __restrict__ sums  = g_sum[rank];
    const float* __restrict__ gsums = g_gsum[rank];
    const float* __restrict__ maxs  = g_max[rank];

    if (tid < 8) cs[tid] = g_cnt[rank][seg0 + tid];
    __syncthreads();

    for (int idx = tid; idx < 8 * 512; idx += 256) {
        int s = idx >> 9;
        int k = idx & 511;
        int seg = seg0 + s;
        float v;
        if (k < 128)      v = sums[seg * H + k];
        else if (k < 256) v = sums[seg * H + (k - 128)] / fmaxf(cs[s], 1.f);
        else if (k < 384) v = (cs[s] > 0.f) ? maxs[seg * H + (k - 256)] : 0.f;
        else              v = gsums[seg * H + (k - 384)];
        a[s][k] = v;
    }
    __syncthreads();

    int cg = tid & 31;          // column group: cols [cg*4, cg*4+4)
    int kc = tid >> 5;          // K chunk: [kc*64, kc*64+64)
    int k0 = kc * 64;

    float4 r[8];
    #pragma unroll
    for (int s = 0; s < 8; ++s) r[s] = make_float4(0.f, 0.f, 0.f, 0.f);

    const float4* W4 = reinterpret_cast<const float4*>(Wp) + cg;   // row k: W4[k*32]
    #pragma unroll 4
    for (int kk = 0; kk < 16; ++kk) {
        int kb = k0 + kk * 4;
        float4 w0 = W4[(kb + 0) * 32];
        float4 w1 = W4[(kb + 1) * 32];
        float4 w2 = W4[(kb + 2) * 32];
        float4 w3 = W4[(kb + 3) * 32];
        #pragma unroll
        for (int s = 0; s < 8; ++s) {
            float4 av = *reinterpret_cast<const float4*>(&a[s][kb]);
            r[s].x += av.x * w0.x + av.y * w1.x + av.z * w2.x + av.w * w3.x;
            r[s].y += av.x * w0.y + av.y * w1.y + av.z * w2.y + av.w * w3.y;
            r[s].z += av.x * w0.z + av.y * w1.z + av.z * w2.z + av.w * w3.z;
            r[s].w += av.x * w0.w + av.y * w1.w + av.z * w2.w + av.w * w3.w;
        }
    }

    int j = cg * 4;
    if (kc < 7) {
        #pragma unroll
        for (int s = 0; s < 8; ++s)
            *reinterpret_cast<float4*>(&rp[kc][s][j]) = r[s];
    }
    __syncthreads();
    if (kc == 7) {
        float4 bpj = *(reinterpret_cast<const float4*>(bp) + cg);
        #pragma unroll
        for (int s = 0; s < 8; ++s) {
            float4 acc = r[s];
            #pragma unroll
            for (int c = 0; c < 7; ++c) {
                float4 p = *reinterpret_cast<const float4*>(&rp[c][s][j]);
                acc.x += p.x; acc.y += p.y; acc.z += p.z; acc.w += p.w;
            }
            acc.x += bpj.x; acc.y += bpj.y; acc.z += bpj.z; acc.w += bpj.w;
            *reinterpret_cast<float4*>(&g_state[seg0 + s][rank * H + j]) = acc;
        }
    }
}

// ---------------- stage 3: LN + SiLU + MLP + final dot ----------------
// grid: B/4 blocks, 256 threads. cg = tid&31 (4 cols), kc = tid>>5 (48-wide K).
__global__ void final_kernel(const float* __restrict__ gamma, const float* __restrict__ beta,
                             const float* __restrict__ W1,    const float* __restrict__ b1f,
                             const float* __restrict__ W2,    const float* __restrict__ b2f,
                             float* __restrict__ out) {
    int seg0 = blockIdx.x * 4;
    int tid = threadIdx.x;
    int wid = tid >> 5;
    int lane = tid & 31;

    __shared__ float a[4][384];      // 6 KB
    __shared__ float rp[7][4][128];  // 14 KB
    __shared__ float fo[4][128];     // 2 KB

    for (int idx = tid; idx < 4 * 384; idx += 256) {
        int s = idx / 384;
        int k = idx - s * 384;
        a[s][k] = g_state[seg0 + s][k];
    }
    __syncthreads();

    // per-row LayerNorm + SiLU: warp s handles row s
    if (wid < 4) {
        int s = wid;
        float ps = 0.f;
        #pragma unroll
        for (int kk = 0; kk < 12; ++kk) ps += a[s][lane + kk * 32];
        #pragma unroll
        for (int o = 16; o; o >>= 1) ps += __shfl_xor_sync(0xffffffffu, ps, o);
        float mu = ps * (1.f / 384.f);
        float pv = 0.f;
        #pragma unroll
        for (int kk = 0; kk < 12; ++kk) {
            float d = a[s][lane + kk * 32] - mu;
            pv += d * d;
        }
        #pragma unroll
        for (int o = 16; o; o >>= 1) pv += __shfl_xor_sync(0xffffffffu, pv, o);
        float rstd = rsqrtf(pv * (1.f / 384.f) + 1e-5f);
        #pragma unroll
        for (int kk = 0; kk < 12; ++kk) {
            int k = lane + kk * 32;
            float xn = (a[s][k] - mu) * rstd * gamma[k] + beta[k];
            a[s][k] = xn / (1.f + __expf(-xn));   // silu
        }
    }
    __syncthreads();

    int cg = tid & 31;
    int kc = tid >> 5;
    int k0 = kc * 48;

    float4 r[4];
    #pragma unroll
    for (int s = 0; s < 4; ++s) r[s] = make_float4(0.f, 0.f, 0.f, 0.f);

    const float4* W4 = reinterpret_cast<const float4*>(W1) + cg;
    #pragma unroll 4
    for (int kk = 0; kk < 12; ++kk) {
        int kb = k0 + kk * 4;
        float4 w0 = W4[(kb + 0) * 32];
        float4 w1 = W4[(kb + 1) * 32];
        float4 w2 = W4[(kb + 2) * 32];
        float4 w3 = W4[(kb + 3) * 32];
        #pragma unroll
        for (int s = 0; s < 4; ++s) {
            float4 av = *reinterpret_cast<const float4*>(&a[s][kb]);
            r[s].x += av.x * w0.x + av.y * w1.x + av.z * w2.x + av.w * w3.x;
            r[s].y += av.x * w0.y + av.y * w1.y + av.z * w2.y + av.w * w3.y;
            r[s].z += av.x * w0.z + av.y * w1.z + av.z * w2.z + av.w * w3.z;
            r[s].w += av.x * w0.w + av.y * w1.w + av.z * w2.w + av.w * w3.w;
        }
    }

    int j = cg * 4;
    if (kc < 7) {
        #pragma unroll
        for (int s = 0; s < 4; ++s)
            *reinterpret_cast<float4*>(&rp[kc][s][j]) = r[s];
    }
    __syncthreads();
    if (kc == 7) {
        float4 b1j = *(reinterpret_cast<const float4*>(b1f) + cg);
        float4 w2j = *(reinterpret_cast<const float4*>(W2) + cg);
        #pragma unroll
        for (int s = 0; s < 4; ++s) {
            float4 acc = r[s];
            #pragma unroll
            for (int c = 0; c < 7; ++c) {
                float4 p = *reinterpret_cast<const float4*>(&rp[c][s][j]);
                acc.x += p.x; acc.y += p.y; acc.z += p.z; acc.w += p.w;
            }
            acc.x += b1j.x; acc.y += b1j.y; acc.z += b1j.z; acc.w += b1j.w;
            acc.x = acc.x / (1.f + __expf(-acc.x));
            acc.y = acc.y / (1.f + __expf(-acc.y));
            acc.z = acc.z / (1.f + __expf(-acc.z));
            acc.w = acc.w / (1.f + __expf(-acc.w));
            fo[s][j + 0] = acc.x * w2j.x;
            fo[s][j + 1] = acc.y * w2j.y;
            fo[s][j + 2] = acc.z * w2j.z;
            fo[s][j + 3] = acc.w * w2j.w;
        }
    }
    __syncthreads();

    if (wid < 4) {
        int s = wid;
        float p = fo[s][lane] + fo[s][lane + 32] + fo[s][lane + 64] + fo[s][lane + 96];
        #pragma unroll
        for (int o = 16; o; o >>= 1) p += __shfl_xor_sync(0xffffffffu, p, o);
        if (lane == 0) out[seg0 + s] = p + b2f[0];
    }
}

// ---------------- launch ----------------
extern "C" void kernel_launch(void* const* d_in, const int* in_sizes, int n_in,
                              void* d_out, int out_size) {
    const float* h0  = (const float*)d_in[0];
    const float* h1  = (const float*)d_in[1];
    const float* h2  = (const float*)d_in[2];
    const int*   b0  = (const int*)d_in[3];
    const int*   b1  = (const int*)d_in[4];
    const int*   b2  = (const int*)d_in[5];
    const float* Wg0 = (const float*)d_in[6];
    const float* bg0 = (const float*)d_in[7];
    const float* Wg1 = (const float*)d_in[8];
    const float* bg1 = (const float*)d_in[9];
    const float* Wg2 = (const float*)d_in[10];
    const float* bg2 = (const float*)d_in[11];
    const float* Wp0 = (const float*)d_in[12];
    const float* bp0 = (const float*)d_in[13];
    const float* Wp1 = (const float*)d_in[14];
    const float* bp1 = (const float*)d_in[15];
    const float* Wp2 = (const float*)d_in[16];
    const float* bp2 = (const float*)d_in[17];
    const float* gamma = (const float*)d_in[18];
    const float* beta  = (const float*)d_in[19];
    const float* W1  = (const float*)d_in[20];
    const float* b1f = (const float*)d_in[21];
    const float* W2  = (const float*)d_in[22];
    const float* b2f = (const float*)d_in[23];

    int N0 = in_sizes[3];
    int N1 = in_sizes[4];
    int N2 = in_sizes[5];

    init_kernel<<<384, 256>>>();

    dim3 gpool(POOL_BLOCKS_X, RANKS);
    pool_kernel<<<gpool, POOL_THREADS>>>(h0, h1, h2, b0, b1, b2,
                                         Wg0, Wg1, Wg2, bg0, bg1, bg2,
                                         N0, N1, N2);

    dim3 gp(B / 8, RANKS);
    proj_kernel<<<gp, 256>>>(Wp0, bp0, Wp1, bp1, Wp2, bp2);

    final_kernel<<<B / 4, 256>>>(gamma, beta, W1, b1f, W2, b2f, (float*)d_out);
}